// round 2
// baseline (speedup 1.0000x reference)
#include <cuda_runtime.h>
#include <cuda_bf16.h>
#include <cstdint>

// Problem constants
#define NB 4096
#define NR 64
#define ND 512

typedef unsigned long long u64;

// Packed fp32x2 FMA (Blackwell): d = a*b + d  (lane-wise on two packed floats)
__device__ __forceinline__ void fma2(u64 &d, u64 a, u64 b) {
    asm("fma.rn.f32x2 %0, %1, %2, %0;" : "+l"(d) : "l"(a), "l"(b));
}
__device__ __forceinline__ float hsum2(u64 a) {
    float x, y;
    asm("mov.b64 {%0, %1}, %2;" : "=f"(x), "=f"(y) : "l"(a));
    return x + y;
}

__device__ float g_en[NR];       // |e_r|^2
__device__ float g_loss[NB];     // per-b loss

// ---------------------------------------------------------------------------
// Kernel 0: e-row squared norms. 512 threads, warp w handles rows w, w+16, ...
// ---------------------------------------------------------------------------
__global__ void k_en(const float* __restrict__ E) {
    int lane = threadIdx.x & 31;
    int w    = threadIdx.x >> 5;
    for (int r = w; r < NR; r += 16) {
        const ulonglong2* p = (const ulonglong2*)(E + (size_t)r * ND);
        ulonglong2 q0 = p[lane], q1 = p[lane + 32], q2 = p[lane + 64], q3 = p[lane + 96];
        u64 a = 0, b = 0;
        fma2(a, q0.x, q0.x); fma2(b, q0.y, q0.y);
        fma2(a, q1.x, q1.x); fma2(b, q1.y, q1.y);
        fma2(a, q2.x, q2.x); fma2(b, q2.y, q2.y);
        fma2(a, q3.x, q3.x); fma2(b, q3.y, q3.y);
        float s = hsum2(a) + hsum2(b);
        #pragma unroll
        for (int o = 16; o; o >>= 1) s += __shfl_xor_sync(0xffffffffu, s, o);
        if (lane == 0) g_en[r] = s;
    }
}

// ---------------------------------------------------------------------------
// Kernel 1: main. 128 CTAs x 512 threads. 32 b-rows per CTA, E fully in SMEM.
// SMEM layout (floats):
//   sE   : 64 rows x 520 (8-float pad; 2080B rows keep 16B alignment,
//          conflict-free LDS.128 with lane-contiguous addressing)
//   sT   : 16 warps x (32 x 33) transpose scratch (33-pad -> conflict-free)
//   sEn  : 64  (|e|^2)
// ---------------------------------------------------------------------------
#define EPITCH 520
#define SE_FLOATS (NR * EPITCH)            // 33280
#define TPITCH 33
#define ST_FLOATS (16 * 32 * TPITCH)       // 16896
#define SMEM_FLOATS (SE_FLOATS + ST_FLOATS + NR)

__global__ __launch_bounds__(512, 1)
void k_main(const float* __restrict__ W, const float* __restrict__ E,
            const float* __restrict__ L, float* __restrict__ pred) {
    extern __shared__ float smem[];
    float* sE  = smem;
    float* sT  = smem + SE_FLOATS;
    float* sEn = smem + SE_FLOATS + ST_FLOATS;

    const int tid  = threadIdx.x;
    const int lane = tid & 31;
    const int w    = tid >> 5;
    float* sTw = sT + w * 32 * TPITCH;

    // Stage E into SMEM (float4, coalesced)
    const float4* E4 = (const float4*)E;
    for (int i = tid; i < NR * (ND / 4); i += blockDim.x) {
        int r = i >> 7, c = i & 127;
        *(float4*)(sE + r * EPITCH + c * 4) = E4[i];
    }
    if (tid < NR) sEn[tid] = g_en[tid];
    __syncthreads();

    const int b0 = blockIdx.x * 32;

    for (int bi = 0; bi < 2; ++bi) {
        const int b = b0 + w + 16 * bi;

        // --- load w_b into registers as 8 packed f32x2 ---
        u64 wv[8];
        {
            const ulonglong2* W2 = (const ulonglong2*)(W + (size_t)b * ND);
            ulonglong2 q0 = W2[lane], q1 = W2[lane + 32],
                       q2 = W2[lane + 64], q3 = W2[lane + 96];
            wv[0] = q0.x; wv[1] = q0.y; wv[2] = q1.x; wv[3] = q1.y;
            wv[4] = q2.x; wv[5] = q2.y; wv[6] = q3.x; wv[7] = q3.y;
        }

        // --- |w_b|^2 (butterfly -> all lanes) ---
        float wn;
        {
            u64 a = 0, c = 0;
            #pragma unroll
            for (int i = 0; i < 8; i += 2) { fma2(a, wv[i], wv[i]); fma2(c, wv[i+1], wv[i+1]); }
            wn = hsum2(a) + hsum2(c);
            #pragma unroll
            for (int o = 16; o; o >>= 1) wn += __shfl_xor_sync(0xffffffffu, wn, o);
        }

        // --- y = argmax(label[b]) (value desc, index asc on ties) ---
        int y;
        {
            const float* Lr = L + (size_t)b * NR;
            float lv = Lr[lane]; int li = lane;
            float l2 = Lr[lane + 32];
            if (l2 > lv) { lv = l2; li = lane + 32; }
            #pragma unroll
            for (int o = 16; o; o >>= 1) {
                float ov = __shfl_xor_sync(0xffffffffu, lv, o);
                int   oi = __shfl_xor_sync(0xffffffffu, li, o);
                if (ov > lv || (ov == lv && oi < li)) { lv = ov; li = oi; }
            }
            y = li;
        }

        // --- dist^2 over all 64 r, in two chunks of 32 ---
        float v1 = -3.4e38f, v2 = -3.4e38f;
        int   i1 = 0;
        float plus_d2 = 0.0f;

        #pragma unroll 1
        for (int c = 0; c < 2; ++c) {
            float part[32];
            const float* eBase = sE + (size_t)c * 32 * EPITCH;
            #pragma unroll
            for (int rr = 0; rr < 32; ++rr) {
                const ulonglong2* p = (const ulonglong2*)(eBase + rr * EPITCH);
                ulonglong2 e0 = p[lane], e1 = p[lane + 32],
                           e2 = p[lane + 64], e3 = p[lane + 96];
                u64 c0 = 0, c1 = 0;
                fma2(c0, wv[0], e0.x); fma2(c1, wv[1], e0.y);
                fma2(c0, wv[2], e1.x); fma2(c1, wv[3], e1.y);
                fma2(c0, wv[4], e2.x); fma2(c1, wv[5], e2.y);
                fma2(c0, wv[6], e3.x); fma2(c1, wv[7], e3.y);
                part[rr] = hsum2(c0) + hsum2(c1);
            }
            // transpose-reduce through SMEM (conflict-free, no shuffles)
            #pragma unroll
            for (int rr = 0; rr < 32; ++rr) sTw[lane * TPITCH + rr] = part[rr];
            __syncwarp();
            float dot = 0.0f;
            #pragma unroll
            for (int k = 0; k < 32; ++k) dot += sTw[k * TPITCH + lane];
            __syncwarp();

            const int r = c * 32 + lane;          // this lane owns r
            float d2 = wn + sEn[r] - 2.0f * dot;
            if (r == y) plus_d2 = d2;
            if (d2 > v1) { v2 = v1; v1 = d2; i1 = r; }   // r strictly increasing ->
            else if (d2 > v2) { v2 = d2; }               // first-occurrence ties free
        }

        // --- butterfly top-2 merge (all lanes converge to same v1,i1,v2) ---
        #pragma unroll
        for (int o = 16; o; o >>= 1) {
            float ov1 = __shfl_xor_sync(0xffffffffu, v1, o);
            int   oi1 = __shfl_xor_sync(0xffffffffu, i1, o);
            float ov2 = __shfl_xor_sync(0xffffffffu, v2, o);
            if (ov1 > v1 || (ov1 == v1 && oi1 < i1)) {
                v2 = fmaxf(v1, ov2); v1 = ov1; i1 = oi1;
            } else {
                v2 = fmaxf(v2, ov1);
            }
        }

        // plus score lives in lane (y & 31)
        plus_d2 = __shfl_sync(0xffffffffu, plus_d2, y & 31);

        float minus_d2 = (i1 == y) ? v2 : v1;
        if (lane == 0)
            g_loss[b] = 1.0f + sqrtf(fmaxf(plus_d2, 0.0f)) - sqrtf(fmaxf(minus_d2, 0.0f));

        // one-hot pred row
        float* pr = pred + (size_t)b * NR;
        pr[lane]      = (lane == i1)      ? 1.0f : 0.0f;
        pr[lane + 32] = (lane + 32 == i1) ? 1.0f : 0.0f;
    }
}

// ---------------------------------------------------------------------------
// Kernel 2: mean of per-b losses -> out[out_size-1]
// ---------------------------------------------------------------------------
__global__ void k_loss(float* __restrict__ out_loss) {
    __shared__ float sb[512];
    int t = threadIdx.x;
    float s = 0.0f;
    for (int i = t; i < NB; i += 512) s += g_loss[i];
    sb[t] = s;
    __syncthreads();
    for (int o = 256; o; o >>= 1) {
        if (t < o) sb[t] += sb[t + o];
        __syncthreads();
    }
    if (t == 0) *out_loss = sb[0] * (1.0f / (float)NB);
}

extern "C" void kernel_launch(void* const* d_in, const int* in_sizes, int n_in,
                              void* d_out, int out_size) {
    // Robust input binding by element count
    const float* W = nullptr; const float* E = nullptr; const float* L = nullptr;
    for (int i = 0; i < n_in; ++i) {
        if      (in_sizes[i] == NB * ND) W = (const float*)d_in[i];
        else if (in_sizes[i] == NR * ND) E = (const float*)d_in[i];
        else if (in_sizes[i] == NB * NR) L = (const float*)d_in[i];
    }
    float* out   = (float*)d_out;
    float* pred  = out;                    // [4096,64] one-hot
    float* lossp = out + (out_size - 1);   // scalar loss last

    size_t smem_bytes = (size_t)SMEM_FLOATS * sizeof(float);   // ~201KB
    cudaFuncSetAttribute(k_main, cudaFuncAttributeMaxDynamicSharedMemorySize,
                         (int)smem_bytes);

    k_en  <<<1,   512>>>(E);
    k_main<<<128, 512, smem_bytes>>>(W, E, L, pred);
    k_loss<<<1,   512>>>(lossp);
}

// round 6
// speedup vs baseline: 1.3597x; 1.3597x over previous
#include <cuda_runtime.h>
#include <cstdint>

#define NB 4096
#define NR 64
#define ND 512
#define D2 256              // ND/2
#define BPC 32              // b-rows per CTA
#define GRID (NB / BPC)     // 128

typedef unsigned long long u64;

__device__ __forceinline__ void fma2(u64 &d, u64 a, u64 b) {
    asm("fma.rn.f32x2 %0, %1, %2, %0;" : "+l"(d) : "l"(a), "l"(b));
}
__device__ __forceinline__ u64 add2(u64 a, u64 b) {
    u64 r; asm("add.rn.f32x2 %0, %1, %2;" : "=l"(r) : "l"(a), "l"(b)); return r;
}
__device__ __forceinline__ u64 dup2(float f) {
    u64 r; asm("mov.b64 %0, {%1, %1};" : "=l"(r) : "f"(f)); return r;
}
__device__ __forceinline__ void unpack2(u64 v, float &lo, float &hi) {
    asm("mov.b64 {%0, %1}, %2;" : "=f"(lo), "=f"(hi) : "l"(v));
}

__device__ float g_part[GRID];
__device__ int   g_ctr = 0;

// ---- dynamic smem layout (bytes) ----
#define OFF_E   0
#define SZ_E    (D2 * 512)            // [d2][r] float2, 512B rows   = 131072
#define WPITCH  4112                  // 257*16 B per b-pair (16B-aligned, bank-skewed)
#define OFF_W   (OFF_E + SZ_E)
#define SZ_W    (16 * WPITCH)         // 65792
#define OFF_EN  (OFF_W + SZ_W)        // 64 f
#define OFF_WN  (OFF_EN + 256)        // 32 f
#define OFF_Y   (OFF_WN + 128)        // 32 i
#define OFF_LS  (OFF_Y + 128)         // 32 f
#define OFF_PE  (OFF_LS + 128)        // 256 f
#define OFF_PW  (OFF_PE + 1024)       // 256 f
#define SMEM_TOTAL (OFF_PW + 1024)    // 199552 B

__global__ __launch_bounds__(256, 1)
void k_fused(const float* __restrict__ W, const float* __restrict__ E,
             const float* __restrict__ Lb, float* __restrict__ pred,
             float* __restrict__ lossp) {
    extern __shared__ char sm[];
    float* sE  = (float*)(sm + OFF_E);
    char*  sW  = sm + OFF_W;
    float* sEn = (float*)(sm + OFF_EN);
    float* sWn = (float*)(sm + OFF_WN);
    int*   sY  = (int*)(sm + OFF_Y);
    float* sLs = (float*)(sm + OFF_LS);
    float* sPE = (float*)(sm + OFF_PE);
    float* sPW = (float*)(sm + OFF_PW);
    __shared__ int sFlag;

    const int t  = threadIdx.x;
    const int L  = t & 31;
    const int b0 = blockIdx.x * BPC;

    // ---------- stage E: gmem [r][d] -> smem [d2][r] float2; fused |e|^2 ----------
    {
        const int r = t & 63, g = t >> 6;
        const float4* Er = (const float4*)(E + (size_t)r * ND);
        float enp = 0.f;
        #pragma unroll 4
        for (int k = 0; k < 32; ++k) {
            int c = g + (k << 2);
            float4 v = Er[c];
            enp = fmaf(v.x, v.x, enp); enp = fmaf(v.y, v.y, enp);
            enp = fmaf(v.z, v.z, enp); enp = fmaf(v.w, v.w, enp);
            // lanes are consecutive r -> 8B stride -> conflict-free STS.64
            *(float2*)((char*)sE + (size_t)(2 * c)     * 512 + r * 8) = make_float2(v.x, v.y);
            *(float2*)((char*)sE + (size_t)(2 * c + 1) * 512 + r * 8) = make_float2(v.z, v.w);
        }
        sPE[t] = enp;
    }
    // ---------- stage W: pair-interleaved [pair][d2]{lo(d),hi(d),lo(d+1),hi(d+1)}; fused |w|^2 ----------
    {
        const int b = t & 31, g = t >> 5;
        const float4* Wb = (const float4*)(W + (size_t)(b0 + b) * ND);
        char* base = sW + (b >> 1) * WPITCH + (b & 1) * 4;
        float wnp = 0.f;
        #pragma unroll 4
        for (int k = 0; k < 16; ++k) {
            int c = g + (k << 3);
            float4 v = Wb[c];
            wnp = fmaf(v.x, v.x, wnp); wnp = fmaf(v.y, v.y, wnp);
            wnp = fmaf(v.z, v.z, wnp); wnp = fmaf(v.w, v.w, wnp);
            char* p0 = base + (size_t)(2 * c) * 16;
            *(float*)(p0)      = v.x;   // d2=2c,   d-parity 0
            *(float*)(p0 + 8)  = v.y;   // d2=2c,   d-parity 1
            *(float*)(p0 + 16) = v.z;   // d2=2c+1, d-parity 0
            *(float*)(p0 + 24) = v.w;   // d2=2c+1, d-parity 1
        }
        sPW[t] = wnp;
    }
    __syncthreads();

    u64 acc[4][2][2] = {};   // [b-pair][r of lane's 2][d-parity], f32x2 packed over b-pair

    if (t < 128) {
        // ================= mainloop: warp = 8b x 64r =================
        const int wi = t >> 5;
        const char* eb = (const char*)sE + L * 16;          // lane owns r = 2L, 2L+1
        const char* wb = sW + (wi * 4) * WPITCH;            // 4 b-pairs
        #pragma unroll 4
        for (int d2 = 0; d2 < D2; ++d2) {
            float4 e4 = *(const float4*)(eb + (size_t)d2 * 512);
            u64 dr0a = dup2(e4.x), dr0b = dup2(e4.y);       // r=2L  : d, d+1
            u64 dr1a = dup2(e4.z), dr1b = dup2(e4.w);       // r=2L+1: d, d+1
            #pragma unroll
            for (int p = 0; p < 4; ++p) {
                ulonglong2 q = *(const ulonglong2*)(wb + p * WPITCH + d2 * 16);
                fma2(acc[p][0][0], q.x, dr0a);
                fma2(acc[p][0][1], q.y, dr0b);
                fma2(acc[p][1][0], q.x, dr1a);
                fma2(acc[p][1][1], q.y, dr1b);
            }
        }
    } else {
        // ================= helper warps: norm combine + label argmax =================
        const int u = t - 128;
        if (u < 64) sEn[u] = sPE[u] + sPE[u + 64] + sPE[u + 128] + sPE[u + 192];
        if (u < 32) {
            float s = 0.f;
            #pragma unroll
            for (int k = 0; k < 8; ++k) s += sPW[u + 32 * k];
            sWn[u] = s;
        }
        const int wh = (t >> 5) - 4;
        #pragma unroll
        for (int j = 0; j < 8; ++j) {
            int bl = wh * 8 + j;
            const float* Lr = Lb + (size_t)(b0 + bl) * NR;
            float lv = Lr[L]; int li = L;
            float l2 = Lr[L + 32];
            if (l2 > lv) { lv = l2; li = L + 32; }   // strict > keeps lower index on ties
            #pragma unroll
            for (int o = 16; o; o >>= 1) {
                float ov = __shfl_xor_sync(0xffffffffu, lv, o);
                int   oi = __shfl_xor_sync(0xffffffffu, li, o);
                if (ov > lv || (ov == lv && oi < li)) { lv = ov; li = oi; }
            }
            if (L == 0) sY[bl] = li;
        }
    }
    __syncthreads();

    // ================= epilogue (warps 0-3): top-2 / argmax / loss / pred =================
    if (t < 128) {
        const int wi = t >> 5;
        float2 en2 = *(const float2*)(sEn + 2 * L);
        #pragma unroll
        for (int p = 0; p < 4; ++p) {
            u64 s0 = add2(acc[p][0][0], acc[p][0][1]);  // dot(b-pair, r=2L)
            u64 s1 = add2(acc[p][1][0], acc[p][1][1]);  // dot(b-pair, r=2L+1)
            float d0lo, d0hi, d1lo, d1hi;
            unpack2(s0, d0lo, d0hi);
            unpack2(s1, d1lo, d1hi);
            #pragma unroll
            for (int s = 0; s < 2; ++s) {
                int bl = wi * 8 + p * 2 + s;
                float dot0 = s ? d0hi : d0lo;
                float dot1 = s ? d1hi : d1lo;
                float wn = sWn[bl];
                int   y  = sY[bl];
                float da = fmaf(-2.f, dot0, wn + en2.x);   // dist^2(b, 2L)
                float db = fmaf(-2.f, dot1, wn + en2.y);   // dist^2(b, 2L+1)
                float v1, v2; int i1;
                if (db > da) { v1 = db; i1 = 2 * L + 1; v2 = da; }
                else         { v1 = da; i1 = 2 * L;     v2 = db; }
                float pys = (y & 1) ? db : da;
                #pragma unroll
                for (int o = 16; o; o >>= 1) {
                    float ov1 = __shfl_xor_sync(0xffffffffu, v1, o);
                    int   oi1 = __shfl_xor_sync(0xffffffffu, i1, o);
                    float ov2 = __shfl_xor_sync(0xffffffffu, v2, o);
                    if (ov1 > v1 || (ov1 == v1 && oi1 < i1)) {
                        v2 = fmaxf(v1, ov2); v1 = ov1; i1 = oi1;
                    } else {
                        v2 = fmaxf(v2, ov1);
                    }
                }
                float plus  = __shfl_sync(0xffffffffu, pys, y >> 1);
                float minus = (i1 == y) ? v2 : v1;
                if (L == 0)
                    sLs[bl] = 1.0f + sqrtf(fmaxf(plus, 0.f)) - sqrtf(fmaxf(minus, 0.f));
                float2 pr = make_float2((2 * L == i1) ? 1.f : 0.f,
                                        (2 * L + 1 == i1) ? 1.f : 0.f);
                *(float2*)(pred + (size_t)(b0 + bl) * NR + 2 * L) = pr;
            }
        }
    }
    __syncthreads();

    // ================= per-CTA loss partial + deterministic last-CTA mean =================
    if (t < 32) {
        float s = sLs[t];
        #pragma unroll
        for (int o = 16; o; o >>= 1) s += __shfl_xor_sync(0xffffffffu, s, o);
        if (t == 0) {
            g_part[blockIdx.x] = s;
            __threadfence();
            int old = atomicAdd(&g_ctr, 1);
            sFlag = (old == GRID - 1) ? 1 : 0;
        }
    }
    __syncthreads();
    if (sFlag && t < 32) {
        float s = 0.f;
        #pragma unroll
        for (int k = 0; k < GRID / 32; ++k) {
            float v;
            asm("ld.global.cg.f32 %0, [%1];" : "=f"(v) : "l"(g_part + t + 32 * k));
            s += v;
        }
        #pragma unroll
        for (int o = 16; o; o >>= 1) s += __shfl_xor_sync(0xffffffffu, s, o);
        if (t == 0) { *lossp = s * (1.0f / (float)NB); g_ctr = 0; }
    }
}

extern "C" void kernel_launch(void* const* d_in, const int* in_sizes, int n_in,
                              void* d_out, int out_size) {
    const float* W = nullptr; const float* E = nullptr; const float* L = nullptr;
    for (int i = 0; i < n_in; ++i) {
        if      (in_sizes[i] == NB * ND) W = (const float*)d_in[i];
        else if (in_sizes[i] == NR * ND) E = (const float*)d_in[i];
        else if (in_sizes[i] == NB * NR) L = (const float*)d_in[i];
    }
    float* out = (float*)d_out;
    cudaFuncSetAttribute(k_fused, cudaFuncAttributeMaxDynamicSharedMemorySize, SMEM_TOTAL);
    k_fused<<<GRID, 256, SMEM_TOTAL>>>(W, E, L, out, out + (out_size - 1));
}